// round 11
// baseline (speedup 1.0000x reference)
#include <cuda_runtime.h>
#include <math.h>

#define NPART 512
#define NB    16
#define HIDN  100
#define WPB   2            // warps per block
#define NI    8            // particles i per warp
#define TPB   64

typedef unsigned long long u64;

__device__ __forceinline__ float ex2f(float x) {
    float y; asm("ex2.approx.ftz.f32 %0, %1;" : "=f"(y) : "f"(x)); return y;
}
__device__ __forceinline__ float lg2f(float x) {
    float y; asm("lg2.approx.ftz.f32 %0, %1;" : "=f"(y) : "f"(x)); return y;
}
__device__ __forceinline__ float rsq_a(float x) {
    float y; asm("rsqrt.approx.ftz.f32 %0, %1;" : "=f"(y) : "f"(x)); return y;
}
__device__ __forceinline__ float rcp_a(float x) {
    float y; asm("rcp.approx.ftz.f32 %0, %1;" : "=f"(y) : "f"(x)); return y;
}

// fast softplus: max(x,0) + ln(1+exp(-|x|)) via ex2/lg2
__device__ __forceinline__ float softplus_fast(float x) {
    const float L2E = 1.4426950408889634f;
    const float LN2 = 0.6931471805599453f;
    float e = ex2f(-fabsf(x) * L2E);
    float l = lg2f(1.0f + e) * LN2;
    return fmaxf(x, 0.0f) + l;
}

// ---- packed f32x2 helpers (sm_100+) ----
__device__ __forceinline__ u64 pk2(float lo, float hi) {
    u64 d; asm("mov.b64 %0, {%1, %2};" : "=l"(d) : "f"(lo), "f"(hi)); return d;
}
__device__ __forceinline__ void upk2(u64 v, float& lo, float& hi) {
    asm("mov.b64 {%0, %1}, %2;" : "=f"(lo), "=f"(hi) : "l"(v));
}
__device__ __forceinline__ u64 fma2(u64 a, u64 b, u64 c) {
    u64 d; asm("fma.rn.f32x2 %0, %1, %2, %3;" : "=l"(d) : "l"(a), "l"(b), "l"(c)); return d;
}
__device__ __forceinline__ u64 mul2(u64 a, u64 b) {
    u64 d; asm("mul.rn.f32x2 %0, %1, %2;" : "=l"(d) : "l"(a), "l"(b)); return d;
}
__device__ __forceinline__ u64 add2(u64 a, u64 b) {
    u64 d; asm("add.rn.f32x2 %0, %1, %2;" : "=l"(d) : "l"(a), "l"(b)); return d;
}
__device__ __forceinline__ u64 ex2p(u64 a) {
    float lo, hi; upk2(a, lo, hi);
    return pk2(ex2f(lo), ex2f(hi));
}
__device__ __forceinline__ u64 rsqp(u64 a) {
    float lo, hi; upk2(a, lo, hi);
    return pk2(rsq_a(lo), rsq_a(hi));
}
__device__ __forceinline__ u64 rcpp(u64 a) {
    float lo, hi; upk2(a, lo, hi);
    return pk2(rcp_a(lo), rcp_a(hi));
}

struct Acc { u64 vyp, vx, F, G, Gxx, Gyy; };

// per-pair vortex interaction (packed 2 j's). Accumulates vyp = +Sum F*dx.
// G/Gxx/Gyy accumulate with Fp (HALF of G2); doubled in feature assembly.
__device__ __forceinline__ void pair_body(
    u64 yi2, u64 xi2, u64 yj, u64 xj, u64 ml2e, u64 mc, u64 md,
    u64 t2p, u64 is2, u64 nhc, u64 ndd, Acc& a,
    u64 ones, u64 nones, u64 eps2)
{
    u64 dy  = fma2(yj, nones, yi2);            // yi - yj
    u64 dx  = fma2(xj, nones, xi2);            // xi - xj
    u64 sq  = fma2(dy, dy, mul2(dx, dx));
    u64 s   = add2(sq, eps2);
    u64 rs  = rsqp(s);                         // 1/sqrt(s)
    u64 r   = mul2(s, rs);                     // sqrt(s)
    u64 ivs = mul2(rs, rs);                    // 1/s
    u64 e1  = ex2p(mul2(sq, ml2e));            // exp(-sq/sig^2)
    u64 e2  = ex2p(fma2(mc, r, mul2(md, sq))); // exp(-c r - d sq)
    u64 g   = fma2(e1, nones, ones);           // 1 - e1 (== 0 for j==i)
    u64 A   = mul2(t2p, ivs);                  // tau/(2 pi s)
    u64 Ae2 = mul2(A, e2);
    u64 F   = mul2(Ae2, g);                    // falloff
    u64 is2e1 = mul2(is2, e1);
    u64 mivs  = fma2(ivs, nones, ndd);         // -d - 1/s
    u64 t2n   = fma2(nhc, rs, mivs);           // -(c/(2r) + d + 1/s)
    u64 inner = fma2(g, t2n, is2e1);           // is2*e1 - g*t2
    u64 Fp  = mul2(Ae2, inner);                // dF/d(sq)  (= G2/2)
    a.vyp = fma2(F, dx, a.vyp);
    a.vx  = fma2(F, dy, a.vx);
    a.F   = add2(a.F, F);
    u64 gdy = mul2(Fp, dy);
    u64 gdx = mul2(Fp, dx);
    a.G   = fma2(gdy, dx, a.G);                // half of SG
    a.Gxx = fma2(gdx, dx, a.Gxx);              // half of SGxx
    a.Gyy = fma2(gdy, dy, a.Gyy);              // half of SGyy
}

// ---- single fused kernel: raw-input mainloop, no prep, no smem ----
__global__ __launch_bounds__(TPB)
void vortex_kernel(const float* __restrict__ inp,
                   const float* __restrict__ W1,
                   const float* __restrict__ b1,
                   const float* __restrict__ W2,
                   const float* __restrict__ b2,
                   float* __restrict__ out)
{
    const int tid   = threadIdx.x;
    const int ipb   = WPB * NI;                // 16 i's per block
    const int bpb   = NPART / ipb;             // 32 blocks per batch
    const int b     = blockIdx.x / bpb;
    const int ig    = blockIdx.x % bpb;
    const int warp  = tid >> 5;
    const int lane  = tid & 31;
    const int ibase = ig * ipb + warp * NI;    // this warp's first particle

    const float L2E    = 1.4426950408889634f;
    const float INV2PI = 0.15915494309189535f;

    // per-i scalars
    const float* pp[NI];
    float yi[NI], xi[NI];
    u64 yp[NI], xp[NI];
    #pragma unroll
    for (int q = 0; q < NI; ++q) {
        pp[q] = inp + ((size_t)b * NPART + ibase + q) * 6;
        yi[q] = __ldg(pp[q] + 0);
        xi[q] = __ldg(pp[q] + 1);
        yp[q] = pk2(yi[q], yi[q]);
        xp[q] = pk2(xi[q], xi[q]);
    }

    const u64 ones   = pk2(1.0f, 1.0f);
    const u64 nones  = pk2(-1.0f, -1.0f);
    const u64 eps2   = pk2(1e-6f, 1e-6f);
    const u64 nl2e   = pk2(-L2E, -L2E);
    const u64 pi2p   = pk2(INV2PI, INV2PI);
    const u64 nhalf  = pk2(-0.5f, -0.5f);

    // batch base as float4 stream: 12 floats per packed j-pair = 3 float4
    const float4* __restrict__ ip4 = (const float4*)(inp + (size_t)b * NPART * 6);

    Acc acc[NI];
    #pragma unroll
    for (int q = 0; q < NI; ++q) acc[q] = (Acc){0,0,0,0,0,0};

    #pragma unroll 1
    for (int jj = 0; jj < NPART / 64; ++jj) {
        int idx = jj * 32 + lane;              // packed j-pair index (0..255)
        float4 A4 = __ldg(&ip4[idx * 3 + 0]);  // y0 x0 tau0 sig0
        float4 B4 = __ldg(&ip4[idx * 3 + 1]);  // c0 d0 y1 x1
        float4 C4 = __ldg(&ip4[idx * 3 + 2]);  // tau1 sig1 c1 d1

        u64 yj   = pk2(A4.x, B4.z);
        u64 xj   = pk2(A4.y, B4.w);
        u64 tauv = pk2(A4.z, C4.x);
        u64 sigv = pk2(A4.w, C4.y);
        u64 cv   = pk2(B4.x, C4.z);
        u64 dv   = pk2(B4.y, C4.w);

        u64 is2  = rcpp(mul2(sigv, sigv));     // 1/sig^2
        u64 ml2e = mul2(is2, nl2e);            // -is2*log2e
        u64 mc   = mul2(cv, nl2e);             // -c*log2e
        u64 md   = mul2(dv, nl2e);             // -d*log2e
        u64 t2p  = mul2(tauv, pi2p);           // tau/2pi
        u64 nhc  = mul2(cv, nhalf);            // -c/2
        u64 ndd  = mul2(dv, nones);            // -d

        #pragma unroll
        for (int q = 0; q < NI; ++q)
            pair_body(yp[q], xp[q], yj, xj, ml2e, mc, md, t2p, is2, nhc, ndd,
                      acc[q], ones, nones, eps2);
    }

    // ---- horizontal add of packed halves, then warp butterfly reduce ----
    float red[6 * NI];
    #pragma unroll
    for (int q = 0; q < NI; ++q) {
        float l, h;
        upk2(acc[q].vyp, l, h); red[q * 6 + 0] = l + h;
        upk2(acc[q].vx,  l, h); red[q * 6 + 1] = l + h;
        upk2(acc[q].F,   l, h); red[q * 6 + 2] = l + h;
        upk2(acc[q].G,   l, h); red[q * 6 + 3] = l + h;
        upk2(acc[q].Gxx, l, h); red[q * 6 + 4] = l + h;
        upk2(acc[q].Gyy, l, h); red[q * 6 + 5] = l + h;
    }
    #pragma unroll
    for (int o = 16; o; o >>= 1) {
        #pragma unroll
        for (int m = 0; m < 6 * NI; ++m)
            red[m] += __shfl_xor_sync(0xffffffffu, red[m], o);
    }

    // features: tau, sig, c, d, vy, vx, dvy/dy, dvy/dx, dvx/dy, dvx/dx
    // G/Gxx/Gyy reductions hold HALF values -> double here.
    float feat[NI][10];
    float tau_[NI], sig_[NI];
    #pragma unroll
    for (int q = 0; q < NI; ++q) {
        float SG   = red[q * 6 + 3] * 2.0f;
        float SGxx = red[q * 6 + 4] * 2.0f;
        float SGyy = red[q * 6 + 5] * 2.0f;
        float SF   = red[q * 6 + 2];
        tau_[q] = __ldg(pp[q] + 2);
        sig_[q] = __ldg(pp[q] + 3);
        feat[q][0] = tau_[q];
        feat[q][1] = sig_[q];
        feat[q][2] = __ldg(pp[q] + 4);
        feat[q][3] = __ldg(pp[q] + 5);
        feat[q][4] = -red[q * 6 + 0];   // vy
        feat[q][5] = red[q * 6 + 1];    // vx
        feat[q][6] = -SG;               // dvy/dy
        feat[q][7] = -(SGxx + SF);      // dvy/dx
        feat[q][8] = SGyy + SF;         // dvx/dy
        feat[q][9] = SG;                // dvx/dx
    }

    // ---- MLP 10 -> 100 (LeakyReLU 0.1) -> 6, weights shared across 8 i's ----
    float po[NI][6];
    #pragma unroll
    for (int q = 0; q < NI; ++q)
        #pragma unroll
        for (int m = 0; m < 6; ++m) po[q][m] = 0.0f;

    #pragma unroll
    for (int rblk = 0; rblk < 4; ++rblk) {
        int k = rblk * 32 + lane;
        if (k < HIDN) {
            float h[NI];
            float bb = __ldg(&b1[k]);
            #pragma unroll
            for (int q = 0; q < NI; ++q) h[q] = bb;
            #pragma unroll
            for (int f = 0; f < 10; ++f) {
                float w = __ldg(&W1[f * HIDN + k]);
                #pragma unroll
                for (int q = 0; q < NI; ++q) h[q] = fmaf(feat[q][f], w, h[q]);
            }
            #pragma unroll
            for (int q = 0; q < NI; ++q)
                h[q] = (h[q] >= 0.0f) ? h[q] : 0.1f * h[q];
            #pragma unroll
            for (int m = 0; m < 6; ++m) {
                float w = __ldg(&W2[k * 6 + m]);         // raw W2, L1-hot
                #pragma unroll
                for (int q = 0; q < NI; ++q) po[q][m] = fmaf(h[q], w, po[q][m]);
            }
        }
    }
    #pragma unroll
    for (int o = 16; o; o >>= 1) {
        #pragma unroll
        for (int q = 0; q < NI; ++q)
            #pragma unroll
            for (int m = 0; m < 6; ++m)
                po[q][m] += __shfl_xor_sync(0xffffffffu, po[q][m], o);
    }

    // ---- epilogue (lane 0 writes all 8 particles, float2 stores) ----
    if (lane == 0) {
        float bb0 = __ldg(&b2[0]), bb1 = __ldg(&b2[1]), bb2 = __ldg(&b2[2]);
        float bb3 = __ldg(&b2[3]), bb4 = __ldg(&b2[4]), bb5 = __ldg(&b2[5]);
        #pragma unroll
        for (int q = 0; q < NI; ++q) {
            float2* op = (float2*)(out + ((size_t)b * NPART + ibase + q) * 6);
            op[0] = make_float2(yi[q]   + 0.1f * (po[q][0] + bb0),
                                xi[q]   + 0.1f * (po[q][1] + bb1));
            op[1] = make_float2(tau_[q] + 0.1f * (po[q][2] + bb2),
                                sig_[q] + 0.1f * (po[q][3] + bb3));
            op[2] = make_float2(0.1f * softplus_fast(po[q][4] + bb4),
                                0.1f * softplus_fast(po[q][5] + bb5));
        }
    }
}

extern "C" void kernel_launch(void* const* d_in, const int* in_sizes, int n_in,
                              void* d_out, int out_size)
{
    const float* inp = (const float*)d_in[0];  // (16,512,6)
    const float* W1  = (const float*)d_in[1];  // (10,100)
    const float* b1  = (const float*)d_in[2];  // (100,)
    const float* W2  = (const float*)d_in[3];  // (100,6)
    const float* b2  = (const float*)d_in[4];  // (6,)
    float* out = (float*)d_out;                // (16,512,6)

    // single launch: 512 blocks of 64 threads, 8 particles/warp
    dim3 grid(NB * (NPART / (WPB * NI)));      // 512
    vortex_kernel<<<grid, TPB>>>(inp, W1, b1, W2, b2, out);
}

// round 13
// speedup vs baseline: 1.1670x; 1.1670x over previous
#include <cuda_runtime.h>
#include <math.h>

#define NPART 512
#define NB    16
#define HIDN  100
#define WPB   2            // warps per block
#define NI    4            // particles i per warp
#define TPB   64

typedef unsigned long long u64;

__device__ __forceinline__ float ex2f(float x) {
    float y; asm("ex2.approx.ftz.f32 %0, %1;" : "=f"(y) : "f"(x)); return y;
}
__device__ __forceinline__ float lg2f(float x) {
    float y; asm("lg2.approx.ftz.f32 %0, %1;" : "=f"(y) : "f"(x)); return y;
}
__device__ __forceinline__ float rsq_a(float x) {
    float y; asm("rsqrt.approx.ftz.f32 %0, %1;" : "=f"(y) : "f"(x)); return y;
}
__device__ __forceinline__ float rcp_a(float x) {
    float y; asm("rcp.approx.ftz.f32 %0, %1;" : "=f"(y) : "f"(x)); return y;
}

// fast softplus: max(x,0) + ln(1+exp(-|x|)) via ex2/lg2
__device__ __forceinline__ float softplus_fast(float x) {
    const float L2E = 1.4426950408889634f;
    const float LN2 = 0.6931471805599453f;
    float e = ex2f(-fabsf(x) * L2E);
    float l = lg2f(1.0f + e) * LN2;
    return fmaxf(x, 0.0f) + l;
}

// ---- packed f32x2 helpers (sm_100+) ----
__device__ __forceinline__ u64 pk2(float lo, float hi) {
    u64 d; asm("mov.b64 %0, {%1, %2};" : "=l"(d) : "f"(lo), "f"(hi)); return d;
}
__device__ __forceinline__ void upk2(u64 v, float& lo, float& hi) {
    asm("mov.b64 {%0, %1}, %2;" : "=f"(lo), "=f"(hi) : "l"(v));
}
__device__ __forceinline__ u64 fma2(u64 a, u64 b, u64 c) {
    u64 d; asm("fma.rn.f32x2 %0, %1, %2, %3;" : "=l"(d) : "l"(a), "l"(b), "l"(c)); return d;
}
__device__ __forceinline__ u64 mul2(u64 a, u64 b) {
    u64 d; asm("mul.rn.f32x2 %0, %1, %2;" : "=l"(d) : "l"(a), "l"(b)); return d;
}
__device__ __forceinline__ u64 add2(u64 a, u64 b) {
    u64 d; asm("add.rn.f32x2 %0, %1, %2;" : "=l"(d) : "l"(a), "l"(b)); return d;
}
__device__ __forceinline__ u64 ex2p(u64 a) {
    float lo, hi; upk2(a, lo, hi);
    return pk2(ex2f(lo), ex2f(hi));
}
__device__ __forceinline__ u64 rsqp(u64 a) {
    float lo, hi; upk2(a, lo, hi);
    return pk2(rsq_a(lo), rsq_a(hi));
}
__device__ __forceinline__ u64 rcpp(u64 a) {
    float lo, hi; upk2(a, lo, hi);
    return pk2(rcp_a(lo), rcp_a(hi));
}

struct Acc { u64 vyp, vx, F, G, Gxx, Gyy; };

// per-pair vortex interaction (packed 2 j's). Accumulates vyp = +Sum F*dx.
// e12 = e1*e2 as one exp2 of summed log2 args; gh = e2 - e12 = (1-e1)e2.
// G/Gxx/Gyy accumulate with Fp (HALF of G2); doubled in feature assembly.
__device__ __forceinline__ void pair_body(
    u64 yi2, u64 xi2, u64 yj, u64 xj, u64 ml2e, u64 mc, u64 md,
    u64 t2p, u64 is2, u64 nhc, u64 ndd, Acc& a,
    u64 nones, u64 eps2)
{
    u64 dy   = fma2(yj, nones, yi2);           // yi - yj
    u64 dx   = fma2(xj, nones, xi2);           // xi - xj
    u64 sq   = fma2(dy, dy, mul2(dx, dx));
    u64 s    = add2(sq, eps2);
    u64 rs   = rsqp(s);                        // 1/sqrt(s)
    u64 r    = mul2(s, rs);                    // sqrt(s)
    u64 ivs  = mul2(rs, rs);                   // 1/s
    u64 mdsq = mul2(md, sq);                   // -d*sq (log2 units)
    u64 arg2 = fma2(mc, r, mdsq);              // log2(e2)
    u64 arg12= fma2(ml2e, sq, arg2);           // log2(e1*e2)
    u64 e2   = ex2p(arg2);                     // exp(-c r - d sq)
    u64 e12  = ex2p(arg12);                    // e1*e2 (== e2 when j==i)
    u64 gh   = fma2(e12, nones, e2);           // (1-e1)*e2
    u64 A    = mul2(t2p, ivs);                 // tau/(2 pi s)
    u64 F    = mul2(A, gh);                    // falloff
    u64 t1   = mul2(is2, e12);                 // is2*e1*e2
    u64 mivs = fma2(ivs, nones, ndd);          // -1/s - d
    u64 t2n  = fma2(nhc, rs, mivs);            // -(c/(2r) + d + 1/s)
    u64 inner= fma2(gh, t2n, t1);              // t1 - gh*t2
    u64 Fp   = mul2(A, inner);                 // dF/d(sq)  (= G2/2)
    a.vyp = fma2(F, dx, a.vyp);
    a.vx  = fma2(F, dy, a.vx);
    a.F   = add2(a.F, F);
    u64 gdy = mul2(Fp, dy);
    u64 gdx = mul2(Fp, dx);
    a.G   = fma2(gdy, dx, a.G);                // half of SG
    a.Gxx = fma2(gdx, dx, a.Gxx);              // half of SGxx
    a.Gyy = fma2(gdy, dy, a.Gyy);              // half of SGyy
}

// ---- single fused kernel: raw-input mainloop, no prep, no smem ----
__global__ __launch_bounds__(TPB, 7)
void vortex_kernel(const float* __restrict__ inp,
                   const float* __restrict__ W1,
                   const float* __restrict__ b1,
                   const float* __restrict__ W2,
                   const float* __restrict__ b2,
                   float* __restrict__ out)
{
    const int tid   = threadIdx.x;
    const int ipb   = WPB * NI;                // 8 i's per block
    const int bpb   = NPART / ipb;             // 64 blocks per batch
    const int b     = blockIdx.x / bpb;
    const int ig    = blockIdx.x % bpb;
    const int warp  = tid >> 5;
    const int lane  = tid & 31;
    const int ibase = ig * ipb + warp * NI;    // this warp's first particle

    const float L2E    = 1.4426950408889634f;
    const float INV2PI = 0.15915494309189535f;

    // per-i scalars
    const float* pp[NI];
    float yi[NI], xi[NI];
    u64 yp[NI], xp[NI];
    #pragma unroll
    for (int q = 0; q < NI; ++q) {
        pp[q] = inp + ((size_t)b * NPART + ibase + q) * 6;
        yi[q] = __ldg(pp[q] + 0);
        xi[q] = __ldg(pp[q] + 1);
        yp[q] = pk2(yi[q], yi[q]);
        xp[q] = pk2(xi[q], xi[q]);
    }

    const u64 nones  = pk2(-1.0f, -1.0f);
    const u64 eps2   = pk2(1e-6f, 1e-6f);
    const u64 nl2e   = pk2(-L2E, -L2E);
    const u64 pi2p   = pk2(INV2PI, INV2PI);
    const u64 nhalf  = pk2(-0.5f, -0.5f);

    // batch base as float4 stream: 12 floats per packed j-pair = 3 float4
    const float4* __restrict__ ip4 = (const float4*)(inp + (size_t)b * NPART * 6);

    Acc acc[NI];
    #pragma unroll
    for (int q = 0; q < NI; ++q) acc[q] = (Acc){0,0,0,0,0,0};

    #pragma unroll 2
    for (int jj = 0; jj < NPART / 64; ++jj) {
        int idx = jj * 32 + lane;              // packed j-pair index (0..255)
        float4 A4 = __ldg(&ip4[idx * 3 + 0]);  // y0 x0 tau0 sig0
        float4 B4 = __ldg(&ip4[idx * 3 + 1]);  // c0 d0 y1 x1
        float4 C4 = __ldg(&ip4[idx * 3 + 2]);  // tau1 sig1 c1 d1

        u64 yj   = pk2(A4.x, B4.z);
        u64 xj   = pk2(A4.y, B4.w);
        u64 tauv = pk2(A4.z, C4.x);
        u64 sigv = pk2(A4.w, C4.y);
        u64 cv   = pk2(B4.x, C4.z);
        u64 dv   = pk2(B4.y, C4.w);

        u64 is2  = rcpp(mul2(sigv, sigv));     // 1/sig^2
        u64 ml2e = mul2(is2, nl2e);            // -is2*log2e
        u64 mc   = mul2(cv, nl2e);             // -c*log2e
        u64 md   = mul2(dv, nl2e);             // -d*log2e
        u64 t2p  = mul2(tauv, pi2p);           // tau/2pi
        u64 nhc  = mul2(cv, nhalf);            // -c/2
        u64 ndd  = mul2(dv, nones);            // -d

        #pragma unroll
        for (int q = 0; q < NI; ++q)
            pair_body(yp[q], xp[q], yj, xj, ml2e, mc, md, t2p, is2, nhc, ndd,
                      acc[q], nones, eps2);
    }

    // ---- horizontal add of packed halves, pack into 12 u64, butterfly ----
    u64 redp[3 * NI];     // 12 packed values = 24 floats
    #pragma unroll
    for (int q = 0; q < NI; ++q) {
        float l, h, vyp_, vx_, F_, G_, Gxx_, Gyy_;
        upk2(acc[q].vyp, l, h); vyp_ = l + h;
        upk2(acc[q].vx,  l, h); vx_  = l + h;
        upk2(acc[q].F,   l, h); F_   = l + h;
        upk2(acc[q].G,   l, h); G_   = l + h;
        upk2(acc[q].Gxx, l, h); Gxx_ = l + h;
        upk2(acc[q].Gyy, l, h); Gyy_ = l + h;
        redp[q * 3 + 0] = pk2(vyp_, vx_);
        redp[q * 3 + 1] = pk2(F_,   G_);
        redp[q * 3 + 2] = pk2(Gxx_, Gyy_);
    }
    #pragma unroll
    for (int o = 16; o; o >>= 1) {
        #pragma unroll
        for (int m = 0; m < 3 * NI; ++m)
            redp[m] = add2(redp[m], __shfl_xor_sync(0xffffffffu, redp[m], o));
    }

    // features: tau, sig, c, d, vy, vx, dvy/dy, dvy/dx, dvx/dy, dvx/dx
    // G/Gxx/Gyy reductions hold HALF values -> double here.
    float feat[NI][10];
    float tau_[NI], sig_[NI];
    #pragma unroll
    for (int q = 0; q < NI; ++q) {
        float vyp_, vx_, F_, G_, Gxx_, Gyy_;
        upk2(redp[q * 3 + 0], vyp_, vx_);
        upk2(redp[q * 3 + 1], F_,   G_);
        upk2(redp[q * 3 + 2], Gxx_, Gyy_);
        float SG   = G_   * 2.0f;
        float SGxx = Gxx_ * 2.0f;
        float SGyy = Gyy_ * 2.0f;
        tau_[q] = __ldg(pp[q] + 2);
        sig_[q] = __ldg(pp[q] + 3);
        feat[q][0] = tau_[q];
        feat[q][1] = sig_[q];
        feat[q][2] = __ldg(pp[q] + 4);
        feat[q][3] = __ldg(pp[q] + 5);
        feat[q][4] = -vyp_;             // vy
        feat[q][5] = vx_;               // vx
        feat[q][6] = -SG;               // dvy/dy
        feat[q][7] = -(SGxx + F_);      // dvy/dx
        feat[q][8] = SGyy + F_;         // dvx/dy
        feat[q][9] = SG;                // dvx/dx
    }

    // ---- MLP 10 -> 100 (LeakyReLU 0.1) -> 6, weights shared across 4 i's ----
    float po[NI][6];
    #pragma unroll
    for (int q = 0; q < NI; ++q)
        #pragma unroll
        for (int m = 0; m < 6; ++m) po[q][m] = 0.0f;

    #pragma unroll
    for (int rblk = 0; rblk < 4; ++rblk) {
        int k = rblk * 32 + lane;
        if (k < HIDN) {
            float h[NI];
            float bb = __ldg(&b1[k]);
            #pragma unroll
            for (int q = 0; q < NI; ++q) h[q] = bb;
            #pragma unroll
            for (int f = 0; f < 10; ++f) {
                float w = __ldg(&W1[f * HIDN + k]);
                #pragma unroll
                for (int q = 0; q < NI; ++q) h[q] = fmaf(feat[q][f], w, h[q]);
            }
            #pragma unroll
            for (int q = 0; q < NI; ++q)
                h[q] = fmaxf(h[q], 0.1f * h[q]);         // LeakyReLU(0.1)
            #pragma unroll
            for (int m = 0; m < 6; ++m) {
                float w = __ldg(&W2[k * 6 + m]);         // raw W2, L1-hot
                #pragma unroll
                for (int q = 0; q < NI; ++q) po[q][m] = fmaf(h[q], w, po[q][m]);
            }
        }
    }

    // pack MLP partials (pairs of q share a u64) and butterfly-reduce
    u64 pop[3 * NI];      // po[q][m]: pack (q, m) and (q, m+1) per u64... use m-pairs
    #pragma unroll
    for (int q = 0; q < NI; ++q) {
        pop[q * 3 + 0] = pk2(po[q][0], po[q][1]);
        pop[q * 3 + 1] = pk2(po[q][2], po[q][3]);
        pop[q * 3 + 2] = pk2(po[q][4], po[q][5]);
    }
    #pragma unroll
    for (int o = 16; o; o >>= 1) {
        #pragma unroll
        for (int m = 0; m < 3 * NI; ++m)
            pop[m] = add2(pop[m], __shfl_xor_sync(0xffffffffu, pop[m], o));
    }

    // ---- epilogue (lane 0 writes all 4 particles, float2 stores) ----
    if (lane == 0) {
        float bb0 = __ldg(&b2[0]), bb1 = __ldg(&b2[1]), bb2 = __ldg(&b2[2]);
        float bb3 = __ldg(&b2[3]), bb4 = __ldg(&b2[4]), bb5 = __ldg(&b2[5]);
        #pragma unroll
        for (int q = 0; q < NI; ++q) {
            float p0, p1, p2, p3, p4, p5;
            upk2(pop[q * 3 + 0], p0, p1);
            upk2(pop[q * 3 + 1], p2, p3);
            upk2(pop[q * 3 + 2], p4, p5);
            float2* op = (float2*)(out + ((size_t)b * NPART + ibase + q) * 6);
            op[0] = make_float2(yi[q]   + 0.1f * (p0 + bb0),
                                xi[q]   + 0.1f * (p1 + bb1));
            op[1] = make_float2(tau_[q] + 0.1f * (p2 + bb2),
                                sig_[q] + 0.1f * (p3 + bb3));
            op[2] = make_float2(0.1f * softplus_fast(p4 + bb4),
                                0.1f * softplus_fast(p5 + bb5));
        }
    }
}

extern "C" void kernel_launch(void* const* d_in, const int* in_sizes, int n_in,
                              void* d_out, int out_size)
{
    const float* inp = (const float*)d_in[0];  // (16,512,6)
    const float* W1  = (const float*)d_in[1];  // (10,100)
    const float* b1  = (const float*)d_in[2];  // (100,)
    const float* W2  = (const float*)d_in[3];  // (100,6)
    const float* b2  = (const float*)d_in[4];  // (6,)
    float* out = (float*)d_out;                // (16,512,6)

    // single launch: 1024 blocks of 64 threads, 4 particles/warp
    dim3 grid(NB * (NPART / (WPB * NI)));      // 1024
    vortex_kernel<<<grid, TPB>>>(inp, W1, b1, W2, b2, out);
}

// round 14
// speedup vs baseline: 1.2018x; 1.0298x over previous
#include <cuda_runtime.h>
#include <math.h>

#define NPART 512
#define NB    16
#define HIDN  100
#define WPB   2            // warps per block
#define NI    4            // particles i per warp
#define TPB   64

typedef unsigned long long u64;

__device__ __forceinline__ float ex2f(float x) {
    float y; asm("ex2.approx.ftz.f32 %0, %1;" : "=f"(y) : "f"(x)); return y;
}
__device__ __forceinline__ float lg2f(float x) {
    float y; asm("lg2.approx.ftz.f32 %0, %1;" : "=f"(y) : "f"(x)); return y;
}
__device__ __forceinline__ float rsq_a(float x) {
    float y; asm("rsqrt.approx.ftz.f32 %0, %1;" : "=f"(y) : "f"(x)); return y;
}
__device__ __forceinline__ float rcp_a(float x) {
    float y; asm("rcp.approx.ftz.f32 %0, %1;" : "=f"(y) : "f"(x)); return y;
}

// fast softplus: max(x,0) + ln(1+exp(-|x|)) via ex2/lg2
__device__ __forceinline__ float softplus_fast(float x) {
    const float L2E = 1.4426950408889634f;
    const float LN2 = 0.6931471805599453f;
    float e = ex2f(-fabsf(x) * L2E);
    float l = lg2f(1.0f + e) * LN2;
    return fmaxf(x, 0.0f) + l;
}

// ---- packed f32x2 helpers (sm_100+) ----
__device__ __forceinline__ u64 pk2(float lo, float hi) {
    u64 d; asm("mov.b64 %0, {%1, %2};" : "=l"(d) : "f"(lo), "f"(hi)); return d;
}
__device__ __forceinline__ void upk2(u64 v, float& lo, float& hi) {
    asm("mov.b64 {%0, %1}, %2;" : "=f"(lo), "=f"(hi) : "l"(v));
}
__device__ __forceinline__ u64 fma2(u64 a, u64 b, u64 c) {
    u64 d; asm("fma.rn.f32x2 %0, %1, %2, %3;" : "=l"(d) : "l"(a), "l"(b), "l"(c)); return d;
}
__device__ __forceinline__ u64 mul2(u64 a, u64 b) {
    u64 d; asm("mul.rn.f32x2 %0, %1, %2;" : "=l"(d) : "l"(a), "l"(b)); return d;
}
__device__ __forceinline__ u64 add2(u64 a, u64 b) {
    u64 d; asm("add.rn.f32x2 %0, %1, %2;" : "=l"(d) : "l"(a), "l"(b)); return d;
}
__device__ __forceinline__ u64 ex2p(u64 a) {
    float lo, hi; upk2(a, lo, hi);
    return pk2(ex2f(lo), ex2f(hi));
}
__device__ __forceinline__ u64 rsqp(u64 a) {
    float lo, hi; upk2(a, lo, hi);
    return pk2(rsq_a(lo), rsq_a(hi));
}
__device__ __forceinline__ u64 rcpp(u64 a) {
    float lo, hi; upk2(a, lo, hi);
    return pk2(rcp_a(lo), rcp_a(hi));
}

struct Acc { u64 vyp, vx, F, G, Gxx, Gyy; };

// per-pair vortex interaction (packed 2 j's). Accumulates vyp = +Sum F*dx.
// e12 = e1*e2 as one exp2 of summed log2 args; gh = e2 - e12 = (1-e1)e2.
// G/Gxx/Gyy accumulate with Fp (HALF of G2); doubled in feature assembly.
__device__ __forceinline__ void pair_body(
    u64 yi2, u64 xi2, u64 yj, u64 xj, u64 ml2e, u64 mc, u64 md,
    u64 t2p, u64 is2, u64 nhc, u64 ndd, Acc& a,
    u64 nones, u64 eps2)
{
    u64 dy   = fma2(yj, nones, yi2);           // yi - yj
    u64 dx   = fma2(xj, nones, xi2);           // xi - xj
    u64 sq   = fma2(dy, dy, mul2(dx, dx));
    u64 s    = add2(sq, eps2);
    u64 rs   = rsqp(s);                        // 1/sqrt(s)
    u64 r    = mul2(s, rs);                    // sqrt(s)
    u64 ivs  = mul2(rs, rs);                   // 1/s
    u64 mdsq = mul2(md, sq);                   // -d*sq (log2 units)
    u64 arg2 = fma2(mc, r, mdsq);              // log2(e2)
    u64 arg12= fma2(ml2e, sq, arg2);           // log2(e1*e2)
    u64 e2   = ex2p(arg2);                     // exp(-c r - d sq)
    u64 e12  = ex2p(arg12);                    // e1*e2 (== e2 when j==i)
    u64 gh   = fma2(e12, nones, e2);           // (1-e1)*e2
    u64 A    = mul2(t2p, ivs);                 // tau/(2 pi s)
    u64 F    = mul2(A, gh);                    // falloff
    u64 t1   = mul2(is2, e12);                 // is2*e1*e2
    u64 mivs = fma2(ivs, nones, ndd);          // -1/s - d
    u64 t2n  = fma2(nhc, rs, mivs);            // -(c/(2r) + d + 1/s)
    u64 inner= fma2(gh, t2n, t1);              // t1 - gh*t2
    u64 Fp   = mul2(A, inner);                 // dF/d(sq)  (= G2/2)
    a.vyp = fma2(F, dx, a.vyp);
    a.vx  = fma2(F, dy, a.vx);
    a.F   = add2(a.F, F);
    u64 gdy = mul2(Fp, dy);
    u64 gdx = mul2(Fp, dx);
    a.G   = fma2(gdy, dx, a.G);                // half of SG
    a.Gxx = fma2(gdx, dx, a.Gxx);              // half of SGxx
    a.Gyy = fma2(gdy, dy, a.Gyy);              // half of SGyy
}

// ---- single fused kernel: raw-input mainloop, no prep, no smem ----
__global__ __launch_bounds__(TPB, 7)
void vortex_kernel(const float* __restrict__ inp,
                   const float* __restrict__ W1,
                   const float* __restrict__ b1,
                   const float* __restrict__ W2,
                   const float* __restrict__ b2,
                   float* __restrict__ out)
{
    const int tid   = threadIdx.x;
    const int ipb   = WPB * NI;                // 8 i's per block
    const int bpb   = NPART / ipb;             // 64 blocks per batch
    const int b     = blockIdx.x / bpb;
    const int ig    = blockIdx.x % bpb;
    const int warp  = tid >> 5;
    const int lane  = tid & 31;
    const int ibase = ig * ipb + warp * NI;    // this warp's first particle

    const float L2E    = 1.4426950408889634f;
    const float INV2PI = 0.15915494309189535f;

    // per-i scalars
    const float* pp[NI];
    float yi[NI], xi[NI];
    u64 yp[NI], xp[NI];
    #pragma unroll
    for (int q = 0; q < NI; ++q) {
        pp[q] = inp + ((size_t)b * NPART + ibase + q) * 6;
        yi[q] = __ldg(pp[q] + 0);
        xi[q] = __ldg(pp[q] + 1);
        yp[q] = pk2(yi[q], yi[q]);
        xp[q] = pk2(xi[q], xi[q]);
    }

    const u64 nones  = pk2(-1.0f, -1.0f);
    const u64 eps2   = pk2(1e-6f, 1e-6f);
    const u64 nl2e   = pk2(-L2E, -L2E);
    const u64 pi2p   = pk2(INV2PI, INV2PI);
    const u64 nhalf  = pk2(-0.5f, -0.5f);

    // batch base as float4 stream: 12 floats per packed j-pair = 3 float4
    const float4* __restrict__ ip4 = (const float4*)(inp + (size_t)b * NPART * 6);

    Acc acc[NI];
    #pragma unroll
    for (int q = 0; q < NI; ++q) acc[q] = (Acc){0,0,0,0,0,0};

    #pragma unroll 4
    for (int jj = 0; jj < NPART / 64; ++jj) {
        int idx = jj * 32 + lane;              // packed j-pair index (0..255)
        float4 A4 = __ldg(&ip4[idx * 3 + 0]);  // y0 x0 tau0 sig0
        float4 B4 = __ldg(&ip4[idx * 3 + 1]);  // c0 d0 y1 x1
        float4 C4 = __ldg(&ip4[idx * 3 + 2]);  // tau1 sig1 c1 d1

        u64 yj   = pk2(A4.x, B4.z);
        u64 xj   = pk2(A4.y, B4.w);
        u64 tauv = pk2(A4.z, C4.x);
        u64 sigv = pk2(A4.w, C4.y);
        u64 cv   = pk2(B4.x, C4.z);
        u64 dv   = pk2(B4.y, C4.w);

        u64 is2  = rcpp(mul2(sigv, sigv));     // 1/sig^2
        u64 ml2e = mul2(is2, nl2e);            // -is2*log2e
        u64 mc   = mul2(cv, nl2e);             // -c*log2e
        u64 md   = mul2(dv, nl2e);             // -d*log2e
        u64 t2p  = mul2(tauv, pi2p);           // tau/2pi
        u64 nhc  = mul2(cv, nhalf);            // -c/2
        u64 ndd  = mul2(dv, nones);            // -d

        #pragma unroll
        for (int q = 0; q < NI; ++q)
            pair_body(yp[q], xp[q], yj, xj, ml2e, mc, md, t2p, is2, nhc, ndd,
                      acc[q], nones, eps2);
    }

    // ---- horizontal add of packed halves, pack into 12 u64, butterfly ----
    u64 redp[3 * NI];     // 12 packed values = 24 floats
    #pragma unroll
    for (int q = 0; q < NI; ++q) {
        float l, h, vyp_, vx_, F_, G_, Gxx_, Gyy_;
        upk2(acc[q].vyp, l, h); vyp_ = l + h;
        upk2(acc[q].vx,  l, h); vx_  = l + h;
        upk2(acc[q].F,   l, h); F_   = l + h;
        upk2(acc[q].G,   l, h); G_   = l + h;
        upk2(acc[q].Gxx, l, h); Gxx_ = l + h;
        upk2(acc[q].Gyy, l, h); Gyy_ = l + h;
        redp[q * 3 + 0] = pk2(vyp_, vx_);
        redp[q * 3 + 1] = pk2(F_,   G_);
        redp[q * 3 + 2] = pk2(Gxx_, Gyy_);
    }
    #pragma unroll
    for (int o = 16; o; o >>= 1) {
        #pragma unroll
        for (int m = 0; m < 3 * NI; ++m)
            redp[m] = add2(redp[m], __shfl_xor_sync(0xffffffffu, redp[m], o));
    }

    // features: tau, sig, c, d, vy, vx, dvy/dy, dvy/dx, dvx/dy, dvx/dx
    // G/Gxx/Gyy reductions hold HALF values -> double here.
    float feat[NI][10];
    float tau_[NI], sig_[NI];
    #pragma unroll
    for (int q = 0; q < NI; ++q) {
        float vyp_, vx_, F_, G_, Gxx_, Gyy_;
        upk2(redp[q * 3 + 0], vyp_, vx_);
        upk2(redp[q * 3 + 1], F_,   G_);
        upk2(redp[q * 3 + 2], Gxx_, Gyy_);
        float SG   = G_   * 2.0f;
        float SGxx = Gxx_ * 2.0f;
        float SGyy = Gyy_ * 2.0f;
        tau_[q] = __ldg(pp[q] + 2);
        sig_[q] = __ldg(pp[q] + 3);
        feat[q][0] = tau_[q];
        feat[q][1] = sig_[q];
        feat[q][2] = __ldg(pp[q] + 4);
        feat[q][3] = __ldg(pp[q] + 5);
        feat[q][4] = -vyp_;             // vy
        feat[q][5] = vx_;               // vx
        feat[q][6] = -SG;               // dvy/dy
        feat[q][7] = -(SGxx + F_);      // dvy/dx
        feat[q][8] = SGyy + F_;         // dvx/dy
        feat[q][9] = SG;                // dvx/dx
    }

    // ---- MLP 10 -> 100 (LeakyReLU 0.1) -> 6, weights shared across 4 i's ----
    float po[NI][6];
    #pragma unroll
    for (int q = 0; q < NI; ++q)
        #pragma unroll
        for (int m = 0; m < 6; ++m) po[q][m] = 0.0f;

    #pragma unroll
    for (int rblk = 0; rblk < 4; ++rblk) {
        int k = rblk * 32 + lane;
        if (k < HIDN) {
            float h[NI];
            float bb = __ldg(&b1[k]);
            #pragma unroll
            for (int q = 0; q < NI; ++q) h[q] = bb;
            #pragma unroll
            for (int f = 0; f < 10; ++f) {
                float w = __ldg(&W1[f * HIDN + k]);
                #pragma unroll
                for (int q = 0; q < NI; ++q) h[q] = fmaf(feat[q][f], w, h[q]);
            }
            #pragma unroll
            for (int q = 0; q < NI; ++q)
                h[q] = fmaxf(h[q], 0.1f * h[q]);         // LeakyReLU(0.1)
            #pragma unroll
            for (int m = 0; m < 6; ++m) {
                float w = __ldg(&W2[k * 6 + m]);         // raw W2, L1-hot
                #pragma unroll
                for (int q = 0; q < NI; ++q) po[q][m] = fmaf(h[q], w, po[q][m]);
            }
        }
    }

    // pack MLP partials and butterfly-reduce (u64 shuffles)
    u64 pop[3 * NI];
    #pragma unroll
    for (int q = 0; q < NI; ++q) {
        pop[q * 3 + 0] = pk2(po[q][0], po[q][1]);
        pop[q * 3 + 1] = pk2(po[q][2], po[q][3]);
        pop[q * 3 + 2] = pk2(po[q][4], po[q][5]);
    }
    #pragma unroll
    for (int o = 16; o; o >>= 1) {
        #pragma unroll
        for (int m = 0; m < 3 * NI; ++m)
            pop[m] = add2(pop[m], __shfl_xor_sync(0xffffffffu, pop[m], o));
    }

    // ---- epilogue (lane 0 writes all 4 particles, float2 stores) ----
    if (lane == 0) {
        float bb0 = __ldg(&b2[0]), bb1 = __ldg(&b2[1]), bb2 = __ldg(&b2[2]);
        float bb3 = __ldg(&b2[3]), bb4 = __ldg(&b2[4]), bb5 = __ldg(&b2[5]);
        #pragma unroll
        for (int q = 0; q < NI; ++q) {
            float p0, p1, p2, p3, p4, p5;
            upk2(pop[q * 3 + 0], p0, p1);
            upk2(pop[q * 3 + 1], p2, p3);
            upk2(pop[q * 3 + 2], p4, p5);
            float2* op = (float2*)(out + ((size_t)b * NPART + ibase + q) * 6);
            op[0] = make_float2(yi[q]   + 0.1f * (p0 + bb0),
                                xi[q]   + 0.1f * (p1 + bb1));
            op[1] = make_float2(tau_[q] + 0.1f * (p2 + bb2),
                                sig_[q] + 0.1f * (p3 + bb3));
            op[2] = make_float2(0.1f * softplus_fast(p4 + bb4),
                                0.1f * softplus_fast(p5 + bb5));
        }
    }
}

extern "C" void kernel_launch(void* const* d_in, const int* in_sizes, int n_in,
                              void* d_out, int out_size)
{
    const float* inp = (const float*)d_in[0];  // (16,512,6)
    const float* W1  = (const float*)d_in[1];  // (10,100)
    const float* b1  = (const float*)d_in[2];  // (100,)
    const float* W2  = (const float*)d_in[3];  // (100,6)
    const float* b2  = (const float*)d_in[4];  // (6,)
    float* out = (float*)d_out;                // (16,512,6)

    // single launch: 1024 blocks of 64 threads, 4 particles/warp
    dim3 grid(NB * (NPART / (WPB * NI)));      // 1024
    vortex_kernel<<<grid, TPB>>>(inp, W1, b1, W2, b2, out);
}